// round 8
// baseline (speedup 1.0000x reference)
#include <cuda_runtime.h>
#include <cstdint>

// ---------------- Problem dims ----------------
#define B_DIM   64
#define T_DIM   500
#define IN_DIM  512
#define HID_DIM 2048
#define OUT_DIM 128
#define M_DIM   (B_DIM * T_DIM)          // 32000

// LIF constants
#define A_S1 0.81873075307798182f
#define SC1  0.90634623461009088f
#define A_M1 0.90483741803595952f
#define BM1  0.09516258196404048f
#define TH1  0.5f
#define A_S2 0.90483741803595952f
#define SC2  0.95162581964040482f
#define A_M2 0.95122942450071402f
#define BM2  0.04877057549928598f
#define TH2  1.0f

// ---------------- Scratch (device globals) ----------------
__device__ float g_c1[(size_t)M_DIM * HID_DIM];   // 262 MB: X @ W1
__device__ float g_c2[(size_t)M_DIM * OUT_DIM];   // 16.4 MB: spk1 @ W2

// ---------------- helpers ----------------
__device__ __forceinline__ uint32_t smem_u32(const void* p) {
    uint32_t a;
    asm("{ .reg .u64 t; cvta.to.shared.u64 t, %1; cvt.u32.u64 %0, t; }" : "=r"(a) : "l"(p));
    return a;
}
__device__ __forceinline__ void cp16(uint32_t d, const void* g) {
    asm volatile("cp.async.cg.shared.global [%0], [%1], 16;" :: "r"(d), "l"(g));
}
#define CP_COMMIT() asm volatile("cp.async.commit_group;" ::: "memory")
#define CP_WAIT1()  asm volatile("cp.async.wait_group 1;" ::: "memory")

// ---------------- Pipelined fp32 SGEMM (bit-identical k-order to R1) -------------
// C[M x NG] = A[M x KTOT] @ B[KTOT x NG], row-major. BM=BN=128, BK=16, 256 thr,
// 8x8 microtile. Per output element, k accumulates strictly ascending 0..KTOT-1
// with one fmaf per k -> bit-identical to the R1 baseline SGEMM.
// 3-stage pipeline: B via cp.async, A via LDG->reg->STS (m-major smem layout).
template<int NKC, int KTOT, int NG>
__global__ __launch_bounds__(256, 2)
void sgemm_pipe(const float* __restrict__ A, const float* __restrict__ B,
                float* __restrict__ C)
{
    extern __shared__ float sm[];
    float* As = sm;                 // [3][128][16]  (m-major rows of 16 floats)
    float* Bs = sm + 3 * 128 * 16;  // [3][16][128]

    const int tid  = threadIdx.x;
    const int trow = (tid >> 4) << 3;     // 0..120 step 8
    const int tcol = (tid & 15) << 3;     // 0..120 step 8
    const int m0   = blockIdx.y * 128;
    const int n0   = blockIdx.x * 128;

    float4 areg[2];

    auto ldgA = [&](int c) {
        #pragma unroll
        for (int i = 0; i < 2; i++) {
            int idx = tid + i * 256;
            int m = idx >> 2, k4 = (idx & 3) << 2;
            areg[i] = *reinterpret_cast<const float4*>(
                &A[(size_t)(m0 + m) * KTOT + c * 16 + k4]);
        }
    };
    auto stsA = [&](int s) {
        #pragma unroll
        for (int i = 0; i < 2; i++) {
            int idx = tid + i * 256;
            int m = idx >> 2, k4 = (idx & 3) << 2;
            *reinterpret_cast<float4*>(&As[(s * 128 + m) * 16 + k4]) = areg[i];
        }
    };
    auto cpB = [&](int c) {
        int s = c % 3;
        #pragma unroll
        for (int i = 0; i < 2; i++) {
            int idx = tid + i * 256;
            int r = idx >> 5, c4 = (idx & 31) << 2;
            cp16(smem_u32(&Bs[(s * 16 + r) * 128 + c4]),
                 &B[(size_t)(c * 16 + r) * NG + n0 + c4]);
        }
    };

    float acc[8][8] = {};

    // prologue
    ldgA(0);
    cpB(0); CP_COMMIT();

    for (int i = 0; i < NKC; i++) {
        int s = i % 3;
        stsA(s);                         // stage i: last read by FMA_{i-3}, done
        if (i + 1 < NKC) cpB(i + 1);     // stage i+1: last read by FMA_{i-2}, done
        CP_COMMIT();
        CP_WAIT1();                      // B_i landed (B_{i+1} still in flight)
        __syncthreads();
        if (i + 1 < NKC) ldgA(i + 1);    // hide LDG latency under FMA section

        #pragma unroll
        for (int k = 0; k < 16; k++) {
            float ar[8], br[8];
            #pragma unroll
            for (int u = 0; u < 8; u++)
                ar[u] = As[(s * 128 + trow + u) * 16 + k];   // warp-broadcast scalar LDS
            *reinterpret_cast<float4*>(&br[0]) =
                *reinterpret_cast<const float4*>(&Bs[(s * 16 + k) * 128 + tcol]);
            *reinterpret_cast<float4*>(&br[4]) =
                *reinterpret_cast<const float4*>(&Bs[(s * 16 + k) * 128 + tcol + 4]);
            #pragma unroll
            for (int u = 0; u < 8; u++)
                #pragma unroll
                for (int v = 0; v < 8; v++)
                    acc[u][v] = fmaf(ar[u], br[v], acc[u][v]);
        }
        // single sync per iter is safe: next iter's STS/cp targets differ from
        // any stage still being read (3-stage rotation).
    }

    #pragma unroll
    for (int u = 0; u < 8; u++) {
        #pragma unroll
        for (int v = 0; v < 8; v += 4) {
            float4 w = make_float4(acc[u][v], acc[u][v+1], acc[u][v+2], acc[u][v+3]);
            *reinterpret_cast<float4*>(
                &C[(size_t)(m0 + trow + u) * NG + n0 + tcol + v]) = w;
        }
    }
}

// ---------------- Layer-1 LIF scan ----------------
__global__ __launch_bounds__(256)
void scan1_kernel(const float* __restrict__ c1,
                  float* __restrict__ spk1, float* __restrict__ mems1) {
    int idx = blockIdx.x * blockDim.x + threadIdx.x;
    if (idx >= B_DIM * HID_DIM) return;
    int b = idx >> 11;
    int h = idx & (HID_DIM - 1);
    size_t base = (size_t)b * T_DIM * HID_DIM + h;
    float syn = 0.f, mem = 0.f;
    for (int t = 0; t < T_DIM; t++) {
        size_t o = base + (size_t)t * HID_DIM;
        syn = A_S1 * syn + SC1 * c1[o];
        mem = A_M1 * mem + BM1 * syn;
        float s = (mem - TH1 > 0.f) ? 1.f : 0.f;
        mem -= s * TH1;
        spk1[o]  = s;
        mems1[o] = mem;
    }
}

// ---------------- Layer-2 LIF scan + time reduction ----------------
__global__ __launch_bounds__(128)
void scan2_kernel(const float* __restrict__ c2, float* __restrict__ out,
                  float* __restrict__ spk2, float* __restrict__ mems2) {
    int idx = blockIdx.x * blockDim.x + threadIdx.x;
    if (idx >= B_DIM * OUT_DIM) return;
    int b = idx >> 7;
    int o = idx & (OUT_DIM - 1);
    size_t base = (size_t)b * T_DIM * OUT_DIM + o;
    float syn = 0.f, mem = 0.f, acc = 0.f;
    #pragma unroll 4
    for (int t = 0; t < T_DIM; t++) {
        size_t off = base + (size_t)t * OUT_DIM;
        syn = A_S2 * syn + SC2 * c2[off];
        mem = A_M2 * mem + BM2 * syn;
        float s = (mem - TH2 > 0.f) ? 1.f : 0.f;
        mem -= s * TH2;
        spk2[off]  = s;
        mems2[off] = mem;
        if (t > 0) acc += mem;
    }
    out[(size_t)b * OUT_DIM + o] = acc / (float)T_DIM;
}

// ---------------- Launch ----------------
extern "C" void kernel_launch(void* const* d_in, const int* in_sizes, int n_in,
                              void* d_out, int out_size) {
    const float* x  = (const float*)d_in[0];   // [B, T, IN]
    const float* w1 = (const float*)d_in[1];   // [IN, HID]
    const float* w2 = (const float*)d_in[2];   // [HID, OUT]

    float* out   = (float*)d_out;
    float* spk1  = out  + (size_t)B_DIM * OUT_DIM;
    float* mems1 = spk1 + (size_t)B_DIM * T_DIM * HID_DIM;
    float* spk2  = mems1 + (size_t)B_DIM * T_DIM * HID_DIM;
    float* mems2 = spk2 + (size_t)B_DIM * T_DIM * OUT_DIM;

    float* c1; cudaGetSymbolAddress((void**)&c1, g_c1);
    float* c2; cudaGetSymbolAddress((void**)&c2, g_c2);

    constexpr int SMEM = 3 * 128 * 16 * 4 * 2;   // 49152 bytes

    auto* g1 = sgemm_pipe<IN_DIM / 16, IN_DIM, HID_DIM>;    // K=512
    auto* g2 = sgemm_pipe<HID_DIM / 16, HID_DIM, OUT_DIM>;  // K=2048
    cudaFuncSetAttribute(g1, cudaFuncAttributeMaxDynamicSharedMemorySize, SMEM);
    cudaFuncSetAttribute(g2, cudaFuncAttributeMaxDynamicSharedMemorySize, SMEM);

    // Stage 1: C1 = X @ W1   (M=32000, N=2048, K=512)
    {
        dim3 grid(HID_DIM / 128, M_DIM / 128);   // (16, 250)
        g1<<<grid, 256, SMEM>>>(x, w1, c1);
    }
    // Stage 2: layer-1 scan -> spk1, mems1
    scan1_kernel<<<(B_DIM * HID_DIM) / 256, 256>>>(c1, spk1, mems1);
    // Stage 3: C2 = spk1 @ W2  (M=32000, N=128, K=2048)
    {
        dim3 grid(OUT_DIM / 128, M_DIM / 128);   // (1, 250)
        g2<<<grid, 256, SMEM>>>(spk1, w2, c2);
    }
    // Stage 4: layer-2 scan + output reduction
    scan2_kernel<<<(B_DIM * OUT_DIM) / 128, 128>>>(c2, out, spk2, mems2);
}

// round 10
// speedup vs baseline: 1.2010x; 1.2010x over previous
#include <cuda_runtime.h>
#include <cstdint>

// ---------------- Problem dims ----------------
#define B_DIM   64
#define T_DIM   500
#define IN_DIM  512
#define HID_DIM 2048
#define OUT_DIM 128
#define M_DIM   (B_DIM * T_DIM)          // 32000

// LIF constants
#define A_S1 0.81873075307798182f
#define SC1  0.90634623461009088f
#define A_M1 0.90483741803595952f
#define BM1  0.09516258196404048f
#define TH1  0.5f
#define A_S2 0.90483741803595952f
#define SC2  0.95162581964040482f
#define A_M2 0.95122942450071402f
#define BM2  0.04877057549928598f
#define TH2  1.0f

// ---------------- Scratch (device globals) ----------------
__device__ float    g_c1[(size_t)M_DIM * HID_DIM];   // 262 MB: X @ W1
__device__ float    g_c2[(size_t)M_DIM * OUT_DIM];   // 16.4 MB: spk1 @ W2
__device__ uint32_t g_bm[(size_t)M_DIM * 64];        // 8.2 MB: spike bitmask [m][k/32]

// ---------------- R1 fp32 SGEMM (bit-exact baseline, at FFMA roofline) -----------
#define GBM 128
#define GBN 128
#define GBK 16
#define GTM 8
#define GTN 8

__global__ __launch_bounds__(256, 2)
void sgemm_kernel(const float* __restrict__ A, const float* __restrict__ B,
                  float* __restrict__ C, int M, int N, int K) {
    __shared__ float As[GBK][GBM];   // transposed A tile
    __shared__ float Bs[GBK][GBN];

    const int tid  = threadIdx.x;
    const int brow = blockIdx.y * GBM;
    const int bcol = blockIdx.x * GBN;

    const int trow = (tid / (GBN / GTN)) * GTM;
    const int tcol = (tid % (GBN / GTN)) * GTN;

    float acc[GTM][GTN] = {};
    float ar[GTM], br[GTN];

    for (int k0 = 0; k0 < K; k0 += GBK) {
        #pragma unroll
        for (int i = 0; i < 2; i++) {
            int s   = tid + i * 256;
            int row = s >> 2;
            int kc  = (s & 3) << 2;
            float4 v = *reinterpret_cast<const float4*>(
                &A[(size_t)(brow + row) * K + k0 + kc]);
            As[kc + 0][row] = v.x;
            As[kc + 1][row] = v.y;
            As[kc + 2][row] = v.z;
            As[kc + 3][row] = v.w;
        }
        #pragma unroll
        for (int i = 0; i < 2; i++) {
            int s   = tid + i * 256;
            int row = s >> 5;
            int c4  = (s & 31) << 2;
            *reinterpret_cast<float4*>(&Bs[row][c4]) =
                *reinterpret_cast<const float4*>(
                    &B[(size_t)(k0 + row) * N + bcol + c4]);
        }
        __syncthreads();

        #pragma unroll
        for (int k = 0; k < GBK; k++) {
            #pragma unroll
            for (int i = 0; i < GTM; i++) ar[i] = As[k][trow + i];
            #pragma unroll
            for (int j = 0; j < GTN; j++) br[j] = Bs[k][tcol + j];
            #pragma unroll
            for (int i = 0; i < GTM; i++)
                #pragma unroll
                for (int j = 0; j < GTN; j++)
                    acc[i][j] = fmaf(ar[i], br[j], acc[i][j]);
        }
        __syncthreads();
    }

    #pragma unroll
    for (int i = 0; i < GTM; i++)
        #pragma unroll
        for (int j = 0; j < GTN; j += 4) {
            float4 v = make_float4(acc[i][j], acc[i][j+1], acc[i][j+2], acc[i][j+3]);
            *reinterpret_cast<float4*>(
                &C[(size_t)(brow + trow + i) * N + bcol + tcol + j]) = v;
        }
}

// ---------------- Layer-1 LIF scan (+ spike bitmask via ballot) ----------------
// Warp = 32 consecutive h (32-aligned): one ballot word per (m, h-word).
__global__ __launch_bounds__(256)
void scan1_kernel(const float* __restrict__ c1, float* __restrict__ spk1,
                  float* __restrict__ mems1, uint32_t* __restrict__ bm) {
    int idx = blockIdx.x * blockDim.x + threadIdx.x;
    if (idx >= B_DIM * HID_DIM) return;
    int b = idx >> 11;
    int h = idx & (HID_DIM - 1);
    int lane = threadIdx.x & 31;
    int hw = h >> 5;                       // h-word index 0..63
    size_t base = (size_t)b * T_DIM * HID_DIM + h;
    float syn = 0.f, mem = 0.f;
    for (int t = 0; t < T_DIM; t++) {
        size_t o = base + (size_t)t * HID_DIM;
        syn = A_S1 * syn + SC1 * c1[o];
        mem = A_M1 * mem + BM1 * syn;
        float s = (mem - TH1 > 0.f) ? 1.f : 0.f;
        mem -= s * TH1;
        spk1[o]  = s;
        mems1[o] = mem;
        uint32_t w = __ballot_sync(0xffffffffu, s > 0.f);
        if (lane == 0) {
            size_t m = (size_t)b * T_DIM + t;
            bm[m * 64 + hw] = w;
        }
    }
}

// ---------------- Sparse-exact GEMM2: c2 = spk1 @ w2 via bitmask ----------------
// Bit-identical to dense ascending-k fp32 FMA: skip s=0 (exact no-op),
// acc = RN(acc + w) for s=1 (== fmaf(1,w,acc)).
// Block: 128 rows, 8 warps x 16 rows. w2 staged in smem k-tiles of 64.
// Bitmask word is warp-uniform -> no divergence; set bits iterated ascending.
#define SGK 64
__global__ __launch_bounds__(256, 2)
void spmm2_kernel(const uint32_t* __restrict__ bm, const float* __restrict__ w2,
                  float* __restrict__ c2) {
    __shared__ float ws[SGK][OUT_DIM];

    const int tid  = threadIdx.x;
    const int wid  = tid >> 5;
    const int lane = tid & 31;
    const int rbase = blockIdx.x * 128 + wid * 16;

    float acc[16][4] = {};

    for (int kt = 0; kt < HID_DIM / SGK; kt++) {
        __syncthreads();
        // stage w2[kt*64 .. +63][0..127] densely
        #pragma unroll
        for (int i = 0; i < 8; i++) {
            int s  = tid + i * 256;         // 0..2047
            int kk = s >> 5;                // 0..63
            int c4 = (s & 31) * 4;          // 0..124
            *reinterpret_cast<float4*>(&ws[kk][c4]) =
                *reinterpret_cast<const float4*>(
                    &w2[(size_t)(kt * SGK + kk) * OUT_DIM + c4]);
        }
        __syncthreads();

        #pragma unroll
        for (int r = 0; r < 16; r++) {
            size_t m = (size_t)(rbase + r);
            uint32_t w0 = bm[m * 64 + kt * 2];
            uint32_t w1 = bm[m * 64 + kt * 2 + 1];
            while (w0) {
                int k = __ffs(w0) - 1; w0 &= w0 - 1;
                acc[r][0] += ws[k][lane];
                acc[r][1] += ws[k][lane + 32];
                acc[r][2] += ws[k][lane + 64];
                acc[r][3] += ws[k][lane + 96];
            }
            while (w1) {
                int k = __ffs(w1) - 1; w1 &= w1 - 1;
                acc[r][0] += ws[32 + k][lane];
                acc[r][1] += ws[32 + k][lane + 32];
                acc[r][2] += ws[32 + k][lane + 64];
                acc[r][3] += ws[32 + k][lane + 96];
            }
        }
    }

    #pragma unroll
    for (int r = 0; r < 16; r++) {
        float* cp = &c2[(size_t)(rbase + r) * OUT_DIM];
        cp[lane]      = acc[r][0];
        cp[lane + 32] = acc[r][1];
        cp[lane + 64] = acc[r][2];
        cp[lane + 96] = acc[r][3];
    }
}

// ---------------- Layer-2 LIF scan + time reduction ----------------
__global__ __launch_bounds__(256)
void scan2_kernel(const float* __restrict__ c2, float* __restrict__ out,
                  float* __restrict__ spk2, float* __restrict__ mems2) {
    int idx = blockIdx.x * blockDim.x + threadIdx.x;
    if (idx >= B_DIM * OUT_DIM) return;
    int b = idx >> 7;
    int o = idx & (OUT_DIM - 1);
    size_t base = (size_t)b * T_DIM * OUT_DIM + o;
    float syn = 0.f, mem = 0.f, acc = 0.f;
    for (int t = 0; t < T_DIM; t++) {
        size_t off = base + (size_t)t * OUT_DIM;
        syn = A_S2 * syn + SC2 * c2[off];
        mem = A_M2 * mem + BM2 * syn;
        float s = (mem - TH2 > 0.f) ? 1.f : 0.f;
        mem -= s * TH2;
        spk2[off]  = s;
        mems2[off] = mem;
        if (t > 0) acc += mem;
    }
    out[(size_t)b * OUT_DIM + o] = acc / (float)T_DIM;
}

// ---------------- Launch ----------------
extern "C" void kernel_launch(void* const* d_in, const int* in_sizes, int n_in,
                              void* d_out, int out_size) {
    const float* x  = (const float*)d_in[0];   // [B, T, IN]
    const float* w1 = (const float*)d_in[1];   // [IN, HID]
    const float* w2 = (const float*)d_in[2];   // [HID, OUT]

    float* out   = (float*)d_out;
    float* spk1  = out  + (size_t)B_DIM * OUT_DIM;
    float* mems1 = spk1 + (size_t)B_DIM * T_DIM * HID_DIM;
    float* spk2  = mems1 + (size_t)B_DIM * T_DIM * HID_DIM;
    float* mems2 = spk2 + (size_t)B_DIM * T_DIM * OUT_DIM;

    float*    c1; cudaGetSymbolAddress((void**)&c1, g_c1);
    float*    c2; cudaGetSymbolAddress((void**)&c2, g_c2);
    uint32_t* bm; cudaGetSymbolAddress((void**)&bm, g_bm);

    // Stage 1: C1 = X @ W1   (M=32000, N=2048, K=512) — R1 roofline kernel
    {
        dim3 grid(HID_DIM / GBN, M_DIM / GBM);   // 16 x 250
        sgemm_kernel<<<grid, 256>>>(x, w1, c1, M_DIM, HID_DIM, IN_DIM);
    }
    // Stage 2: layer-1 scan -> spk1, mems1, bitmask
    scan1_kernel<<<(B_DIM * HID_DIM) / 256, 256>>>(c1, spk1, mems1, bm);
    // Stage 3: C2 = spk1 @ W2 via sparse-exact bitmask GEMM
    spmm2_kernel<<<M_DIM / 128, 256>>>(bm, w2, c2);
    // Stage 4: layer-2 scan + output reduction
    scan2_kernel<<<(B_DIM * OUT_DIM) / 256, 256>>>(c2, out, spk2, mems2);
}